// round 2
// baseline (speedup 1.0000x reference)
#include <cuda_runtime.h>
#include <cuda_bf16.h>
#include <stdint.h>

#define BATCH 8
#define NN    1024
#define FF    128

// ---------------- scratch (no allocations allowed -> __device__ globals) ---------
__device__ float g_H[(size_t)BATCH * 12 * NN * FF];        // 48 MB: 12 feature mats per batch
__device__ float g_adjT[(size_t)BATCH * 3 * NN * NN];      // 96 MB: transposed adjs[6..8]
__device__ float g_outacc[(size_t)BATCH * NN * FF];        // 4 MB : self contribution
__device__ float g_part[12][(size_t)BATCH * NN * FF];      // 48 MB: per-op partial outputs
__device__ float g_esrc[BATCH * 12 * NN];
__device__ float g_edst[BATCH * 12 * NN];
__device__ float g_Htot[BATCH * 12 * FF];
__device__ float g_dvec[BATCH * 3 * NN];

// =============================== Phase 1: GEMMs ==================================
// C[1024,128] = X[1024,128] @ W^T[128,128] + bias ; 13 weight sets per batch.
// BM=128, BN=128, BK=16, 256 threads, 8x8 microtile.
__global__ __launch_bounds__(256) void gemm_kernel(
    const float* __restrict__ x,
    const float* __restrict__ fc_w,  const float* __restrict__ fc_b,
    const float* __restrict__ fwd_w, const float* __restrict__ fwd_b,
    const float* __restrict__ bwd_w, const float* __restrict__ bwd_b,
    const float* __restrict__ self_w, const float* __restrict__ self_b,
    const float* __restrict__ bias)
{
    const int rb = blockIdx.x;      // 0..7 row block
    const int r  = blockIdx.y;      // 0..12 weight set
    const int b  = blockIdx.z;      // batch

    const float* X = x + (size_t)b * NN * FF + (size_t)rb * 128 * FF;
    const float* Wp; const float* bv; const float* bv2 = nullptr; float* dst;
    if (r < 6)       { Wp = fc_w  + r * FF * FF;      bv = fc_b  + r * FF;
                       dst = g_H + ((size_t)(b * 12 + r)) * NN * FF; }
    else if (r < 9)  { Wp = fwd_w + (r - 6) * FF * FF; bv = fwd_b + (r - 6) * FF;
                       dst = g_H + ((size_t)(b * 12 + r)) * NN * FF; }
    else if (r < 12) { Wp = bwd_w + (r - 9) * FF * FF; bv = bwd_b + (r - 9) * FF;
                       dst = g_H + ((size_t)(b * 12 + r)) * NN * FF; }
    else             { Wp = self_w; bv = self_b; bv2 = bias;
                       dst = g_outacc + (size_t)b * NN * FF; }

    __shared__ float Xs[16][132];
    __shared__ float Ws[16][132];

    const int tid = threadIdx.x;
    const int ty = tid >> 4, tx = tid & 15;

    float acc[8][8];
    #pragma unroll
    for (int i = 0; i < 8; i++)
        #pragma unroll
        for (int j = 0; j < 8; j++) acc[i][j] = 0.f;

    for (int k0 = 0; k0 < FF; k0 += 16) {
        #pragma unroll
        for (int t = 0; t < 2; t++) {
            int idx = tid + t * 256;          // 0..511 float4 slots
            int row = idx >> 2, kq = idx & 3;
            float4 v = *(const float4*)(X + (size_t)row * FF + k0 + kq * 4);
            Xs[kq * 4 + 0][row] = v.x; Xs[kq * 4 + 1][row] = v.y;
            Xs[kq * 4 + 2][row] = v.z; Xs[kq * 4 + 3][row] = v.w;
            float4 w = *(const float4*)(Wp + (size_t)row * FF + k0 + kq * 4);
            Ws[kq * 4 + 0][row] = w.x; Ws[kq * 4 + 1][row] = w.y;
            Ws[kq * 4 + 2][row] = w.z; Ws[kq * 4 + 3][row] = w.w;
        }
        __syncthreads();
        #pragma unroll
        for (int kk = 0; kk < 16; kk++) {
            float a[8], bb[8];
            *(float4*)(a)     = *(const float4*)&Xs[kk][ty * 8];
            *(float4*)(a + 4) = *(const float4*)&Xs[kk][ty * 8 + 4];
            *(float4*)(bb)     = *(const float4*)&Ws[kk][tx * 8];
            *(float4*)(bb + 4) = *(const float4*)&Ws[kk][tx * 8 + 4];
            #pragma unroll
            for (int i = 0; i < 8; i++)
                #pragma unroll
                for (int j = 0; j < 8; j++) acc[i][j] += a[i] * bb[j];
        }
        __syncthreads();
    }

    float badd[8];
    #pragma unroll
    for (int j = 0; j < 8; j++) {
        badd[j] = bv[tx * 8 + j];
        if (bv2) badd[j] += bv2[tx * 8 + j];
    }
    #pragma unroll
    for (int i = 0; i < 8; i++) {
        int m = rb * 128 + ty * 8 + i;
        float4 o0, o1;
        o0.x = acc[i][0] + badd[0]; o0.y = acc[i][1] + badd[1];
        o0.z = acc[i][2] + badd[2]; o0.w = acc[i][3] + badd[3];
        o1.x = acc[i][4] + badd[4]; o1.y = acc[i][5] + badd[5];
        o1.z = acc[i][6] + badd[6]; o1.w = acc[i][7] + badd[7];
        *(float4*)(dst + (size_t)m * FF + tx * 8)     = o0;
        *(float4*)(dst + (size_t)m * FF + tx * 8 + 4) = o1;
    }
}

// ============================ adj[6..8] transpose ================================
__global__ __launch_bounds__(256) void transpose_kernel(const float* __restrict__ adjs)
{
    __shared__ float t[32][33];
    const int bj = blockIdx.z;                // b*3 + j
    const int b = bj / 3, j = bj % 3;
    const float* A = adjs + ((size_t)(b * 9 + 6 + j)) * NN * NN;
    float* T = g_adjT + (size_t)bj * NN * NN;
    const int x0 = blockIdx.x * 32, y0 = blockIdx.y * 32;
    #pragma unroll
    for (int yy = threadIdx.y; yy < 32; yy += 8)
        t[yy][threadIdx.x] = A[(size_t)(y0 + yy) * NN + x0 + threadIdx.x];
    __syncthreads();
    #pragma unroll
    for (int yy = threadIdx.y; yy < 32; yy += 8)
        T[(size_t)(x0 + yy) * NN + y0 + threadIdx.x] = t[threadIdx.x][yy];
}

// ======================= diagonals of adjs[3..5] =================================
__global__ void dvec_kernel(const float* __restrict__ adjs)
{
    const int i = threadIdx.x, k = blockIdx.y, b = blockIdx.z;
    g_dvec[(b * 3 + k) * NN + i] =
        adjs[(((size_t)(b * 9 + 3 + k)) * NN + i) * NN + i];
}

__global__ void zero_htot_kernel()
{
    int i = blockIdx.x * blockDim.x + threadIdx.x;
    if (i < BATCH * 12 * FF) g_Htot[i] = 0.f;
}

// ==================== attention e-vectors (esrc incl. bias) ======================
__global__ __launch_bounds__(256) void evec_kernel(
    const float* __restrict__ att_w,  const float* __restrict__ att_b,
    const float* __restrict__ fwd_aw, const float* __restrict__ fwd_ab,
    const float* __restrict__ bwd_aw, const float* __restrict__ bwd_ab)
{
    const int op = blockIdx.y, b = blockIdx.z;
    const int warp = threadIdx.x >> 5, lane = threadIdx.x & 31;
    const int row = blockIdx.x * 8 + warp;
    const int hsel = (op < 6) ? op : 5;
    const float* hrow = g_H + (((size_t)b * 12 + hsel) * NN + row) * FF;
    const float* w; float ab;
    if (op < 6)      { w = att_w  + op * 2 * FF;       ab = att_b[op]; }
    else if (op < 9) { w = fwd_aw + (op - 6) * 2 * FF; ab = fwd_ab[op - 6]; }
    else             { w = bwd_aw + (op - 9) * 2 * FF; ab = bwd_ab[op - 9]; }
    float s1 = 0.f, s2 = 0.f;
    #pragma unroll
    for (int q = 0; q < 4; q++) {
        float hv = hrow[lane + 32 * q];
        s1 += hv * w[lane + 32 * q];
        s2 += hv * w[FF + lane + 32 * q];
    }
    #pragma unroll
    for (int off = 16; off > 0; off >>= 1) {
        s1 += __shfl_down_sync(0xffffffffu, s1, off);
        s2 += __shfl_down_sync(0xffffffffu, s2, off);
    }
    if (lane == 0) {
        g_esrc[(b * 12 + op) * NN + row] = s1 + ab;
        g_edst[(b * 12 + op) * NN + row] = s2;
    }
}

// ============================ column sums of H ===================================
__global__ __launch_bounds__(128) void htot_kernel()
{
    const int inst = blockIdx.x;       // b*12+op
    const int rc = blockIdx.y;         // 0..7
    const int f = threadIdx.x;
    const float* Hm = g_H + (size_t)inst * NN * FF;
    float s = 0.f;
    #pragma unroll 4
    for (int r = 0; r < 128; r++) s += Hm[(size_t)(rc * 128 + r) * FF + f];
    atomicAdd(&g_Htot[inst * FF + f], s);
}

// ======================= fused masked attention + aggregation ====================
// out_row = scale * (Htot + sum_edges (exp(lrelu(e))-1)*h_j) / (1024 + sum_edges(exp-1))
// 512 threads = 16 warps x 16 rows; h chunk (256 cols) cached in smem as bf16.
#define CHUNK 256
#define AGG_SMEM (CHUNK * FF * 2 + CHUNK * 4 + CHUNK * 4)

__global__ __launch_bounds__(512) void agg_kernel(const float* __restrict__ adjs)
{
    extern __shared__ __align__(16) char smraw[];
    __nv_bfloat16* hs = (__nv_bfloat16*)smraw;                 // [CHUNK][FF]
    float* edst_s = (float*)(smraw + CHUNK * FF * 2);          // [CHUNK]
    float* ds     = edst_s + CHUNK;                            // [CHUNK]

    const int op = blockIdx.y, b = blockIdx.z;
    const int inst = b * 12 + op;
    const float* Hm = g_H + (size_t)inst * NN * FF;
    const float* adjrow = nullptr;
    const float* dv = nullptr;
    float scale = 1.0f;
    if (op < 3)      adjrow = adjs + ((size_t)(b * 9 + op)) * NN * NN;
    else if (op < 6) dv = g_dvec + (b * 3 + (op - 3)) * NN;
    else if (op < 9) { adjrow = adjs + ((size_t)(b * 9 + op)) * NN * NN; scale = 0.5f; }
    else             { adjrow = g_adjT + ((size_t)(b * 3 + (op - 9))) * NN * NN; scale = 0.5f; }

    const int warp = threadIdx.x >> 5, lane = threadIdx.x & 31;
    const int row0 = blockIdx.x * 256 + warp * 16;
    const float* esrc_g = g_esrc + inst * NN;
    const float* edst_g = g_edst + inst * NN;

    float U[16][4]; float Wsum[16];
    #pragma unroll
    for (int i = 0; i < 16; i++) {
        Wsum[i] = 0.f;
        U[i][0] = U[i][1] = U[i][2] = U[i][3] = 0.f;
    }

    for (int c = 0; c < NN / CHUNK; c++) {
        const int cb = c * CHUNK;
        // load h chunk (fp32 -> bf16 smem)
        for (int t = threadIdx.x; t < CHUNK * 32; t += 512) {
            int jr = t >> 5, q = t & 31;
            float4 v = *(const float4*)(Hm + (size_t)(cb + jr) * FF + q * 4);
            __nv_bfloat162* d2 = (__nv_bfloat162*)(hs + jr * FF + q * 4);
            d2[0] = __floats2bfloat162_rn(v.x, v.y);
            d2[1] = __floats2bfloat162_rn(v.z, v.w);
        }
        if (threadIdx.x < CHUNK) {
            edst_s[threadIdx.x] = edst_g[cb + threadIdx.x];
            ds[threadIdx.x] = dv ? dv[cb + threadIdx.x] : 0.f;
        }
        __syncthreads();

        #pragma unroll
        for (int i = 0; i < 16; i++) {
            const int row = row0 + i;
            bool skip = false;
            if (dv) skip = (__ldg(dv + row) == 0.f);   // uniform warp branch
            if (!skip) {
                const float esri = __ldg(esrc_g + row);
                #pragma unroll
                for (int g = 0; g < 2; g++) {
                    float v4[4];
                    if (adjrow)
                        *(float4*)v4 = *(const float4*)(adjrow + (size_t)row * NN + cb + g * 128 + lane * 4);
                    else
                        *(float4*)v4 = *(const float4*)(ds + g * 128 + lane * 4);
                    #pragma unroll
                    for (int s = 0; s < 4; s++) {
                        unsigned m = __ballot_sync(0xffffffffu, v4[s] > 0.f);
                        while (m) {
                            int bpos = __ffs(m) - 1; m &= m - 1;
                            int jl = g * 128 + bpos * 4 + s;
                            float l = esri + edst_s[jl];
                            l = l > 0.f ? l : 0.01f * l;
                            float w = __expf(l) - 1.0f;
                            Wsum[i] += w;
                            const __nv_bfloat162* hp = (const __nv_bfloat162*)(hs + jl * FF);
                            __nv_bfloat162 p0 = hp[lane];
                            __nv_bfloat162 p1 = hp[32 + lane];
                            U[i][0] += w * __bfloat162float(p0.x);
                            U[i][1] += w * __bfloat162float(p0.y);
                            U[i][2] += w * __bfloat162float(p1.x);
                            U[i][3] += w * __bfloat162float(p1.y);
                        }
                    }
                }
            }
        }
        __syncthreads();
    }

    // epilogue: write per-op partial (no atomics)
    float ht0 = g_Htot[inst * FF + 2 * lane];
    float ht1 = g_Htot[inst * FF + 2 * lane + 1];
    float ht2 = g_Htot[inst * FF + 64 + 2 * lane];
    float ht3 = g_Htot[inst * FF + 65 + 2 * lane];
    float* part = g_part[op] + ((size_t)b * NN + row0) * FF;
    #pragma unroll
    for (int i = 0; i < 16; i++) {
        float inv = scale / (1024.0f + Wsum[i]);
        float2 o0, o1;
        o0.x = (ht0 + U[i][0]) * inv; o0.y = (ht1 + U[i][1]) * inv;
        o1.x = (ht2 + U[i][2]) * inv; o1.y = (ht3 + U[i][3]) * inv;
        *(float2*)(part + (size_t)i * FF + 2 * lane)      = o0;
        *(float2*)(part + (size_t)i * FF + 64 + 2 * lane) = o1;
    }
}

// =========================== final reduce + ReLU =================================
__global__ __launch_bounds__(256) void reduce_kernel(float* __restrict__ out)
{
    const int i = blockIdx.x * blockDim.x + threadIdx.x;   // float4 index
    float4 v = ((const float4*)g_outacc)[i];
    #pragma unroll
    for (int op = 0; op < 12; op++) {
        float4 p = ((const float4*)(g_part[op]))[i];
        v.x += p.x; v.y += p.y; v.z += p.z; v.w += p.w;
    }
    v.x = fmaxf(v.x, 0.f); v.y = fmaxf(v.y, 0.f);
    v.z = fmaxf(v.z, 0.f); v.w = fmaxf(v.w, 0.f);
    ((float4*)out)[i] = v;
}

// ==================================================================================
extern "C" void kernel_launch(void* const* d_in, const int* in_sizes, int n_in,
                              void* d_out, int out_size)
{
    const float* batch_x   = (const float*)d_in[0];
    const float* batch_adjs= (const float*)d_in[1];
    const float* fc_w      = (const float*)d_in[2];
    const float* fc_b      = (const float*)d_in[3];
    const float* att_w     = (const float*)d_in[4];
    const float* att_b     = (const float*)d_in[5];
    const float* fwd_fc_w  = (const float*)d_in[6];
    const float* fwd_fc_b  = (const float*)d_in[7];
    const float* fwd_att_w = (const float*)d_in[8];
    const float* fwd_att_b = (const float*)d_in[9];
    const float* bwd_fc_w  = (const float*)d_in[10];
    const float* bwd_fc_b  = (const float*)d_in[11];
    const float* bwd_att_w = (const float*)d_in[12];
    const float* bwd_att_b = (const float*)d_in[13];
    const float* self_w    = (const float*)d_in[14];
    const float* self_b    = (const float*)d_in[15];
    const float* bias      = (const float*)d_in[16];
    float* out = (float*)d_out;

    static bool attr_done = false;
    if (!attr_done) {
        cudaFuncSetAttribute(agg_kernel, cudaFuncAttributeMaxDynamicSharedMemorySize, AGG_SMEM);
        attr_done = true;
    }

    transpose_kernel<<<dim3(32, 32, 24), dim3(32, 8)>>>(batch_adjs);
    gemm_kernel<<<dim3(8, 13, 8), 256>>>(batch_x, fc_w, fc_b, fwd_fc_w, fwd_fc_b,
                                         bwd_fc_w, bwd_fc_b, self_w, self_b, bias);
    dvec_kernel<<<dim3(1, 3, 8), 1024>>>(batch_adjs);
    zero_htot_kernel<<<12, 1024>>>();
    evec_kernel<<<dim3(128, 12, 8), 256>>>(att_w, att_b, fwd_att_w, fwd_att_b,
                                           bwd_att_w, bwd_att_b);
    htot_kernel<<<dim3(96, 8), 128>>>();
    agg_kernel<<<dim3(4, 12, 8), 512, AGG_SMEM>>>(batch_adjs);
    reduce_kernel<<<1024, 256>>>(out);
}

// round 3
// speedup vs baseline: 1.2080x; 1.2080x over previous
#include <cuda_runtime.h>
#include <cuda_bf16.h>
#include <stdint.h>

#define BATCH 8
#define NN    1024
#define FF    128

// ---------------- scratch (no allocations allowed -> __device__ globals) --------
__device__ float    g_H[(size_t)BATCH * 12 * NN * FF];     // 48 MB
__device__ float    g_outacc[(size_t)BATCH * NN * FF];     // 4 MB (self contribution)
__device__ float    g_part[12][(size_t)BATCH * NN * FF];   // 48 MB per-op partials
__device__ float    g_esrc[BATCH * 12 * NN];
__device__ float    g_edst[BATCH * 12 * NN];
__device__ float    g_Htot[BATCH * 12 * FF];
__device__ uint32_t g_rowbits[(size_t)BATCH * 6 * NN * 32];  // rel 0-2, 6-8 row masks
__device__ uint32_t g_bitsT[(size_t)BATCH * 3 * NN * 32];    // rel 6-8 transposed masks
__device__ uint32_t g_dbits[BATCH * 3 * 32];                 // diag masks (rel 3-5)

// ====================== bitpack A: rel 0-2 row masks ============================
__global__ __launch_bounds__(256) void bitpackA_kernel(const float* __restrict__ adjs)
{
    const int slab = blockIdx.x, mat = blockIdx.y, b = blockIdx.z;
    const int warp = threadIdx.x >> 5, lane = threadIdx.x & 31;
    #pragma unroll
    for (int rr = 0; rr < 4; rr++) {
        const int row = slab * 32 + warp * 4 + rr;
        const float* rp = adjs + (((size_t)(b * 9 + mat)) * NN + row) * NN;
        uint32_t myw = 0;
        #pragma unroll 4
        for (int it = 0; it < 32; it++) {
            float v = rp[it * 32 + lane];
            unsigned mm = __ballot_sync(0xffffffffu, v > 0.f);
            if (lane == it) myw = mm;
        }
        g_rowbits[(((size_t)(b * 6 + mat)) * NN + row) * 32 + lane] = myw;
    }
}

// ============ bitpack B: rel 6-8 row masks + transposed masks ===================
__global__ __launch_bounds__(256) void bitpackB_kernel(const float* __restrict__ adjs)
{
    __shared__ uint32_t sw[32 * 32];
    const int slab = blockIdx.x, mat = blockIdx.y, b = blockIdx.z;
    const int warp = threadIdx.x >> 5, lane = threadIdx.x & 31;
    #pragma unroll
    for (int rr = 0; rr < 4; rr++) {
        const int row = slab * 32 + warp * 4 + rr;
        const float* rp = adjs + (((size_t)(b * 9 + 6 + mat)) * NN + row) * NN;
        uint32_t myw = 0;
        #pragma unroll 4
        for (int it = 0; it < 32; it++) {
            float v = rp[it * 32 + lane];
            unsigned mm = __ballot_sync(0xffffffffu, v > 0.f);
            if (lane == it) myw = mm;
        }
        g_rowbits[(((size_t)(b * 6 + 3 + mat)) * NN + row) * 32 + lane] = myw;
        sw[(warp * 4 + rr) * 32 + lane] = myw;
    }
    __syncthreads();
    for (int c = threadIdx.x; c < NN; c += 256) {
        const int word = c >> 5, bit = c & 31;
        uint32_t t = 0;
        #pragma unroll
        for (int r = 0; r < 32; r++)
            t |= ((sw[r * 32 + word] >> bit) & 1u) << r;
        g_bitsT[(((size_t)(b * 3 + mat)) * NN + c) * 32 + slab] = t;
    }
}

// ============== diag masks (rel 3-5) + zero g_Htot ==============================
__global__ __launch_bounds__(1024) void dbits_kernel(const float* __restrict__ adjs)
{
    const int idx = blockIdx.x;         // b*3 + k
    const int b = idx / 3, k = idx % 3;
    const int i = threadIdx.x, lane = i & 31;
    float v = adjs[(((size_t)(b * 9 + 3 + k)) * NN + i) * NN + i];
    unsigned m = __ballot_sync(0xffffffffu, v > 0.f);
    if (lane == 0) g_dbits[idx * 32 + (i >> 5)] = m;
    if (idx == 0)
        for (int t = threadIdx.x; t < BATCH * 12 * FF; t += 1024) g_Htot[t] = 0.f;
}

// =============================== tf32 GEMM ======================================
// C[1024,128] = X @ W^T + bias ; 13 weight sets per batch. Fragment-swizzled smem.
__device__ __forceinline__ uint32_t f2tf32(float f)
{
    uint32_t r;
    asm("cvt.rna.tf32.f32 %0, %1;" : "=r"(r) : "f"(f));
    return r;
}

__device__ __forceinline__ void mma_tf32(float4& d, const uint4 a, const uint2 b)
{
    asm volatile(
        "mma.sync.aligned.m16n8k8.row.col.f32.tf32.tf32.f32 "
        "{%0,%1,%2,%3}, {%4,%5,%6,%7}, {%8,%9}, {%0,%1,%2,%3};"
        : "+f"(d.x), "+f"(d.y), "+f"(d.z), "+f"(d.w)
        : "r"(a.x), "r"(a.y), "r"(a.z), "r"(a.w), "r"(b.x), "r"(b.y));
}

#define GEMM_SMEM (32768 * 4)   // As 16384 + Ws 16384 uint32

__global__ __launch_bounds__(256) void gemm_kernel(
    const float* __restrict__ x,
    const float* __restrict__ fc_w,  const float* __restrict__ fc_b,
    const float* __restrict__ fwd_w, const float* __restrict__ fwd_b,
    const float* __restrict__ bwd_w, const float* __restrict__ bwd_b,
    const float* __restrict__ self_w, const float* __restrict__ self_b,
    const float* __restrict__ bias)
{
    extern __shared__ uint32_t sm[];
    uint32_t* As = sm;            // [mtile8][kstep16][lane32][reg4]
    uint32_t* Ws = sm + 16384;    // [ntile16][kstep16][lane32][reg2]

    const int rb = blockIdx.x, r = blockIdx.y, b = blockIdx.z;
    const int tid = threadIdx.x;

    const float* X = x + (size_t)b * NN * FF + (size_t)rb * 128 * FF;
    const float* Wp; const float* bv; const float* bv2 = nullptr; float* dst;
    if (r < 6)       { Wp = fc_w  + r * FF * FF;       bv = fc_b  + r * FF;
                       dst = g_H + ((size_t)(b * 12 + r)) * NN * FF; }
    else if (r < 9)  { Wp = fwd_w + (r - 6) * FF * FF; bv = fwd_b + (r - 6) * FF;
                       dst = g_H + ((size_t)(b * 12 + r)) * NN * FF; }
    else if (r < 12) { Wp = bwd_w + (r - 9) * FF * FF; bv = bwd_b + (r - 9) * FF;
                       dst = g_H + ((size_t)(b * 12 + r)) * NN * FF; }
    else             { Wp = self_w; bv = self_b; bv2 = bias;
                       dst = g_outacc + (size_t)b * NN * FF; }

    // ---- fill A fragments (X tile 128x128, tf32) ----
    for (int t = tid; t < 4096; t += 256) {
        const int row = t >> 5;
        const int c = (t & 31) << 2;
        float4 v = *(const float4*)(X + (size_t)row * FF + c);
        const int m = row >> 4, lr = row & 15;
        const int s = c >> 3;
        const int reg = (lr >> 3) + ((c & 4) ? 2 : 0);
        uint32_t* base = As + (((m << 4) + s) << 7) + (((lr & 7) << 2) << 2) + reg;
        base[0]  = f2tf32(v.x);
        base[4]  = f2tf32(v.y);
        base[8]  = f2tf32(v.z);
        base[12] = f2tf32(v.w);
    }
    // ---- fill B fragments (W 128x128, tf32) ----
    for (int t = tid; t < 4096; t += 256) {
        const int n = t >> 5;
        const int k = (t & 31) << 2;
        float4 v = *(const float4*)(Wp + (size_t)n * FF + k);
        const int nt = n >> 3;
        const int s = k >> 3;
        const int reg = (k & 4) ? 1 : 0;
        uint32_t* base = Ws + (((nt << 4) + s) << 6) + (((n & 7) << 2) << 1) + reg;
        base[0] = f2tf32(v.x);
        base[2] = f2tf32(v.y);
        base[4] = f2tf32(v.z);
        base[6] = f2tf32(v.w);
    }
    __syncthreads();

    const int warp = tid >> 5, lane = tid & 31;
    const int wm = warp >> 2, wn = warp & 3;   // warp tile: 64 rows x 32 cols

    float4 acc[4][4];
    #pragma unroll
    for (int i = 0; i < 4; i++)
        #pragma unroll
        for (int j = 0; j < 4; j++) acc[i][j] = make_float4(0.f, 0.f, 0.f, 0.f);

    #pragma unroll
    for (int s = 0; s < 16; s++) {
        uint4 a[4]; uint2 bb[4];
        #pragma unroll
        for (int i = 0; i < 4; i++)
            a[i] = *(const uint4*)(As + ((((wm * 4 + i) << 4) + s) << 7) + (lane << 2));
        #pragma unroll
        for (int j = 0; j < 4; j++)
            bb[j] = *(const uint2*)(Ws + ((((wn * 4 + j) << 4) + s) << 6) + (lane << 1));
        #pragma unroll
        for (int i = 0; i < 4; i++)
            #pragma unroll
            for (int j = 0; j < 4; j++)
                mma_tf32(acc[i][j], a[i], bb[j]);
    }

    const int g = lane >> 2, t4 = lane & 3;
    float b0[4], b1[4];
    #pragma unroll
    for (int j = 0; j < 4; j++) {
        const int col = (wn * 4 + j) * 8 + 2 * t4;
        b0[j] = bv[col];     b1[j] = bv[col + 1];
        if (bv2) { b0[j] += bv2[col]; b1[j] += bv2[col + 1]; }
    }
    #pragma unroll
    for (int i = 0; i < 4; i++) {
        const int row0 = rb * 128 + (wm * 4 + i) * 16 + g;
        #pragma unroll
        for (int j = 0; j < 4; j++) {
            const int col = (wn * 4 + j) * 8 + 2 * t4;
            float2 lo = make_float2(acc[i][j].x + b0[j], acc[i][j].y + b1[j]);
            float2 hi = make_float2(acc[i][j].z + b0[j], acc[i][j].w + b1[j]);
            *(float2*)(dst + (size_t)row0 * FF + col)       = lo;
            *(float2*)(dst + (size_t)(row0 + 8) * FF + col) = hi;
        }
    }

    // ---- fused column-sum (Htot) for the 12 H matrices ----
    if (r < 12) {
        const int inst = b * 12 + r;
        #pragma unroll
        for (int j = 0; j < 4; j++) {
            float s0 = 0.f, s1 = 0.f;
            #pragma unroll
            for (int i = 0; i < 4; i++) {
                s0 += acc[i][j].x + acc[i][j].z;
                s1 += acc[i][j].y + acc[i][j].w;
            }
            #pragma unroll
            for (int off = 16; off >= 4; off >>= 1) {
                s0 += __shfl_down_sync(0xffffffffu, s0, off);
                s1 += __shfl_down_sync(0xffffffffu, s1, off);
            }
            if (lane < 4) {
                const int col = (wn * 4 + j) * 8 + 2 * lane;
                atomicAdd(&g_Htot[inst * FF + col],     s0 + 64.f * bv[col]);
                atomicAdd(&g_Htot[inst * FF + col + 1], s1 + 64.f * bv[col + 1]);
            }
        }
    }
}

// ==================== attention e-vectors (esrc incl. bias) =====================
__global__ __launch_bounds__(256) void evec_kernel(
    const float* __restrict__ att_w,  const float* __restrict__ att_b,
    const float* __restrict__ fwd_aw, const float* __restrict__ fwd_ab,
    const float* __restrict__ bwd_aw, const float* __restrict__ bwd_ab)
{
    const int op = blockIdx.y, b = blockIdx.z;
    const int warp = threadIdx.x >> 5, lane = threadIdx.x & 31;
    const int row = blockIdx.x * 8 + warp;
    const int hsel = (op < 6) ? op : 5;
    const float* hrow = g_H + (((size_t)b * 12 + hsel) * NN + row) * FF;
    const float* w; float ab;
    if (op < 6)      { w = att_w  + op * 2 * FF;       ab = att_b[op]; }
    else if (op < 9) { w = fwd_aw + (op - 6) * 2 * FF; ab = fwd_ab[op - 6]; }
    else             { w = bwd_aw + (op - 9) * 2 * FF; ab = bwd_ab[op - 9]; }
    float s1 = 0.f, s2 = 0.f;
    #pragma unroll
    for (int q = 0; q < 4; q++) {
        float hv = hrow[lane + 32 * q];
        s1 += hv * w[lane + 32 * q];
        s2 += hv * w[FF + lane + 32 * q];
    }
    #pragma unroll
    for (int off = 16; off > 0; off >>= 1) {
        s1 += __shfl_down_sync(0xffffffffu, s1, off);
        s2 += __shfl_down_sync(0xffffffffu, s2, off);
    }
    if (lane == 0) {
        g_esrc[(b * 12 + op) * NN + row] = s1 + ab;
        g_edst[(b * 12 + op) * NN + row] = s2;
    }
}

// ======================= fused masked attention + aggregation ===================
// out_row = scale*(Htot + sum_e (exp(lrelu(e))-1)*h_j) / (1024 + sum_e(exp-1))
#define CHUNK 256
#define AGG_SMEM (CHUNK * FF * 2 + CHUNK * 4)

__global__ __launch_bounds__(512) void agg_kernel()
{
    extern __shared__ __align__(16) char smraw[];
    __nv_bfloat16* hs = (__nv_bfloat16*)smraw;                 // [CHUNK][FF]
    float* edst_s = (float*)(smraw + CHUNK * FF * 2);          // [CHUNK]

    const int op = blockIdx.y, b = blockIdx.z;
    const int inst = b * 12 + op;
    const float* Hm = g_H + (size_t)inst * NN * FF;

    const uint32_t* rowbits = nullptr;
    const uint32_t* dwords = nullptr;
    float scale = 1.0f;
    if (op < 3)      rowbits = g_rowbits + (((size_t)(b * 6 + op)) * NN) * 32;
    else if (op < 6) dwords = g_dbits + (b * 3 + (op - 3)) * 32;
    else if (op < 9) { rowbits = g_rowbits + (((size_t)(b * 6 + op - 3)) * NN) * 32; scale = 0.5f; }
    else             { rowbits = g_bitsT + (((size_t)(b * 3 + op - 9)) * NN) * 32;   scale = 0.5f; }

    const int warp = threadIdx.x >> 5, lane = threadIdx.x & 31;
    const int row0 = blockIdx.x * 256 + warp * 16;
    const float* esrc_g = g_esrc + inst * NN;
    const float* edst_g = g_edst + inst * NN;

    float U[16][4]; float Wsum[16];
    #pragma unroll
    for (int i = 0; i < 16; i++) {
        Wsum[i] = 0.f;
        U[i][0] = U[i][1] = U[i][2] = U[i][3] = 0.f;
    }

    for (int c = 0; c < NN / CHUNK; c++) {
        const int cb = c * CHUNK;
        for (int t = threadIdx.x; t < CHUNK * 32; t += 512) {
            int jr = t >> 5, q = t & 31;
            float4 v = *(const float4*)(Hm + (size_t)(cb + jr) * FF + q * 4);
            __nv_bfloat162* d2 = (__nv_bfloat162*)(hs + jr * FF + q * 4);
            d2[0] = __floats2bfloat162_rn(v.x, v.y);
            d2[1] = __floats2bfloat162_rn(v.z, v.w);
        }
        if (threadIdx.x < CHUNK) edst_s[threadIdx.x] = edst_g[cb + threadIdx.x];
        __syncthreads();

        #pragma unroll
        for (int i = 0; i < 16; i++) {
            const int row = row0 + i;
            bool active = true;
            if (dwords) active = ((__ldg(dwords + (row >> 5)) >> (row & 31)) & 1u) != 0;
            if (active) {
                const uint32_t* mrow = dwords ? (dwords + (cb >> 5))
                                              : (rowbits + (size_t)row * 32 + (cb >> 5));
                uint32_t mw = (lane < 8) ? __ldg(mrow + lane) : 0u;
                const float esri = __ldg(esrc_g + row);
                #pragma unroll
                for (int wi = 0; wi < 8; wi++) {
                    unsigned m = __shfl_sync(0xffffffffu, mw, wi);
                    while (m) {
                        int bpos = __ffs(m) - 1; m &= m - 1;
                        int jl = wi * 32 + bpos;
                        float l = esri + edst_s[jl];
                        l = l > 0.f ? l : 0.01f * l;
                        float w = __expf(l) - 1.0f;
                        Wsum[i] += w;
                        const __nv_bfloat162* hp = (const __nv_bfloat162*)(hs + jl * FF);
                        __nv_bfloat162 p0 = hp[lane];
                        __nv_bfloat162 p1 = hp[32 + lane];
                        U[i][0] += w * __bfloat162float(p0.x);
                        U[i][1] += w * __bfloat162float(p0.y);
                        U[i][2] += w * __bfloat162float(p1.x);
                        U[i][3] += w * __bfloat162float(p1.y);
                    }
                }
            }
        }
        __syncthreads();
    }

    float ht0 = g_Htot[inst * FF + 2 * lane];
    float ht1 = g_Htot[inst * FF + 2 * lane + 1];
    float ht2 = g_Htot[inst * FF + 64 + 2 * lane];
    float ht3 = g_Htot[inst * FF + 65 + 2 * lane];
    float* part = g_part[op] + ((size_t)b * NN + row0) * FF;
    #pragma unroll
    for (int i = 0; i < 16; i++) {
        float inv = scale / (1024.0f + Wsum[i]);
        float2 o0, o1;
        o0.x = (ht0 + U[i][0]) * inv; o0.y = (ht1 + U[i][1]) * inv;
        o1.x = (ht2 + U[i][2]) * inv; o1.y = (ht3 + U[i][3]) * inv;
        *(float2*)(part + (size_t)i * FF + 2 * lane)      = o0;
        *(float2*)(part + (size_t)i * FF + 64 + 2 * lane) = o1;
    }
}

// =========================== final reduce + ReLU ================================
__global__ __launch_bounds__(256) void reduce_kernel(float* __restrict__ out)
{
    const int i = blockIdx.x * blockDim.x + threadIdx.x;   // float4 index
    float4 v = ((const float4*)g_outacc)[i];
    #pragma unroll
    for (int op = 0; op < 12; op++) {
        float4 p = ((const float4*)(g_part[op]))[i];
        v.x += p.x; v.y += p.y; v.z += p.z; v.w += p.w;
    }
    v.x = fmaxf(v.x, 0.f); v.y = fmaxf(v.y, 0.f);
    v.z = fmaxf(v.z, 0.f); v.w = fmaxf(v.w, 0.f);
    ((float4*)out)[i] = v;
}

// ================================================================================
extern "C" void kernel_launch(void* const* d_in, const int* in_sizes, int n_in,
                              void* d_out, int out_size)
{
    const float* batch_x    = (const float*)d_in[0];
    const float* batch_adjs = (const float*)d_in[1];
    const float* fc_w       = (const float*)d_in[2];
    const float* fc_b       = (const float*)d_in[3];
    const float* att_w      = (const float*)d_in[4];
    const float* att_b      = (const float*)d_in[5];
    const float* fwd_fc_w   = (const float*)d_in[6];
    const float* fwd_fc_b   = (const float*)d_in[7];
    const float* fwd_att_w  = (const float*)d_in[8];
    const float* fwd_att_b  = (const float*)d_in[9];
    const float* bwd_fc_w   = (const float*)d_in[10];
    const float* bwd_fc_b   = (const float*)d_in[11];
    const float* bwd_att_w  = (const float*)d_in[12];
    const float* bwd_att_b  = (const float*)d_in[13];
    const float* self_w     = (const float*)d_in[14];
    const float* self_b     = (const float*)d_in[15];
    const float* bias       = (const float*)d_in[16];
    float* out = (float*)d_out;

    static bool attr_done = false;
    if (!attr_done) {
        cudaFuncSetAttribute(agg_kernel, cudaFuncAttributeMaxDynamicSharedMemorySize, AGG_SMEM);
        cudaFuncSetAttribute(gemm_kernel, cudaFuncAttributeMaxDynamicSharedMemorySize, GEMM_SMEM);
        attr_done = true;
    }

    bitpackA_kernel<<<dim3(32, 3, 8), 256>>>(batch_adjs);                 // launch 0
    bitpackB_kernel<<<dim3(32, 3, 8), 256>>>(batch_adjs);                 // launch 1
    dbits_kernel<<<24, 1024>>>(batch_adjs);                               // launch 2
    gemm_kernel<<<dim3(8, 13, 8), 256, GEMM_SMEM>>>(batch_x, fc_w, fc_b, // launch 3
                                                    fwd_fc_w, fwd_fc_b,
                                                    bwd_fc_w, bwd_fc_b,
                                                    self_w, self_b, bias);
    evec_kernel<<<dim3(128, 12, 8), 256>>>(att_w, att_b, fwd_att_w,       // launch 4
                                           fwd_att_b, bwd_att_w, bwd_att_b);
    agg_kernel<<<dim3(4, 12, 8), 512, AGG_SMEM>>>();                      // launch 5 (ncu target)
    reduce_kernel<<<1024, 256>>>(out);                                    // launch 6
}